// round 14
// baseline (speedup 1.0000x reference)
#include <cuda_runtime.h>

#define TT 17
#define TM 16
#define DN 128
#define HH 256
#define PP 128
#define EE 32
#define MM 128

// scratch (no allocations allowed)
__device__ __align__(16) float g_enc[TT*DN*PP];
__device__ __align__(16) float g_A  [TT*DN*MM];
__device__ __align__(16) float g_hg [TT*DN*PP];
__device__ __align__(16) float g_NA [TT*DN*PP];
__device__ __align__(16) float g_CA [TT*DN*PP];
__device__ __align__(16) float g_U  [MM];
__device__ __align__(16) float g_V  [PP];
__device__ int   g_nbr[DN*DN];
__device__ float g_nw [DN*DN];
__device__ int   g_cnt[DN];
__device__ int   g_flag;   // 1 => be==0, rank-1 edge shortcut valid (modulo per-row w<0 check)

// ---------------- cp.async helpers
__device__ __forceinline__ void cp16(void* dst, const void* src){
    unsigned d = (unsigned)__cvta_generic_to_shared(dst);
    asm volatile("cp.async.ca.shared.global [%0], [%1], 16;\n" :: "r"(d), "l"(src));
}
__device__ __forceinline__ void cpcommit(){ asm volatile("cp.async.commit_group;\n"); }
template<int N> __device__ __forceinline__ void cpwait(){ asm volatile("cp.async.wait_group %0;\n" :: "n"(N)); }

// stage a 16x128-float tile (8 KB) with 512 threads (one float4 per thread)
__device__ __forceinline__ void stageT(float* buf, const float* W, int kt, int tid){
    cp16((float4*)buf + tid, (const float4*)W + kt*512 + tid);
}

// ================================================================ K1: encA (4-row tiles, 544 blocks) + init + nbr + prep
__global__ void __launch_bounds__(512) k_front(
        const float* __restrict__ x,  const float* __restrict__ Wn,
        const float* __restrict__ bn, const float* __restrict__ Wm,
        const float* __restrict__ ew, const float* __restrict__ We,
        const float* __restrict__ be, const float* __restrict__ Wc1,
        float* __restrict__ out){
    int bx = blockIdx.x, tid = threadIdx.x;

    if(bx < 544){
        // ---------------- encoder + A projection: 4 node-rows, 1 timestep
        int dt = bx & 31, s = bx >> 5, d0 = dt*4;
        int p = tid & 127, qf = tid >> 7;              // quarter qf owns row qf
        __shared__ __align__(16) float xr[4][HH];      // 4 KB
        __shared__ __align__(16) float wb[2][16*128];  // 16 KB
        __shared__ __align__(16) float hs[4][PP];      // 2 KB  => 22 KB total

        stageT(wb[0], Wn, 0, tid); cpcommit();
        for(int it=tid; it<4*HH; it+=512){
            int h = it>>2, r = it&3;
            xr[r][h] = x[(s*HH+h)*DN + d0 + r];
        }
        float acc = bn[p];

        // GEMM1: enc = relu(x @ Wn + bn), k=256 in 16 tiles of 16
        for(int kt=0; kt<16; kt++){
            if(kt+1 < 16){ stageT(wb[(kt+1)&1], Wn, kt+1, tid); cpcommit(); cpwait<1>(); }
            else cpwait<0>();
            __syncthreads();
            const float* W = wb[kt&1];
            #pragma unroll
            for(int k=0;k<16;k+=4){
                float w0=W[(k  )*128+p], w1=W[(k+1)*128+p];
                float w2=W[(k+2)*128+p], w3=W[(k+3)*128+p];
                float4 xv = *(const float4*)&xr[qf][kt*16+k];
                acc=fmaf(xv.x,w0,acc); acc=fmaf(xv.y,w1,acc);
                acc=fmaf(xv.z,w2,acc); acc=fmaf(xv.w,w3,acc);
            }
            __syncthreads();
        }
        float v = fmaxf(acc, 0.f);
        g_enc[(s*DN+d0+qf)*PP+p] = v;
        hs[qf][p] = v;

        // GEMM2: A = enc @ Wm[:P], k=128 in 8 tiles of 16
        stageT(wb[0], Wm, 0, tid); cpcommit();
        float a2 = 0.f;
        for(int kt=0; kt<8; kt++){
            if(kt+1 < 8){ stageT(wb[(kt+1)&1], Wm, kt+1, tid); cpcommit(); cpwait<1>(); }
            else cpwait<0>();
            __syncthreads();
            const float* W = wb[kt&1];
            #pragma unroll
            for(int k=0;k<16;k+=4){
                float w0=W[(k  )*128+p], w1=W[(k+1)*128+p];
                float w2=W[(k+2)*128+p], w3=W[(k+3)*128+p];
                float4 hv = *(const float4*)&hs[qf][kt*16+k];
                a2=fmaf(hv.x,w0,a2); a2=fmaf(hv.y,w1,a2);
                a2=fmaf(hv.z,w2,a2); a2=fmaf(hv.w,w3,a2);
            }
            __syncthreads();
        }
        g_A[(s*DN+d0+qf)*MM+p] = a2;
        return;
    }
    bx -= 544;

    if(bx < 128){
        // ---------------- init logits region to -1e9 (128 blk * 512 thr * 16B = 1 MB)
        ((float4*)out)[bx*512 + tid] = make_float4(-1e9f,-1e9f,-1e9f,-1e9f);
        return;
    }
    bx -= 128;

    if(bx < 8){
        // ---------------- neighbor lists: one row per warp (16 warps/block)
        int lane = tid & 31, wpi = tid >> 5;
        int i = bx*16 + wpi;
        int off = 0;
        #pragma unroll
        for(int c=0;c<4;c++){
            int j = c*32 + lane;
            float wv = ew[i*DN + j];
            bool pred = (wv > 0.f) || (j == i);
            unsigned m = __ballot_sync(0xffffffffu, pred);
            if(pred){
                int pos = off + __popc(m & ((1u<<lane)-1u));
                g_nbr[i*DN + pos] = j;
                g_nw [i*DN + pos] = wv;
            }
            off += __popc(m);
        }
        if(lane == 0) g_cnt[i] = off;
        return;
    }

    // ---------------- rank-1 edge precompute + flag (single block)
    {
        int p = tid;
        __shared__ __align__(16) float wes[EE];
        __shared__ int bad;
        if(p == 0) bad = 0;
        __syncthreads();
        if(p < EE){
            wes[p] = fmaxf(We[p], 0.f);
            if(be[p] != 0.f) atomicAdd(&bad, 1);
        }
        __syncthreads();
        if(p < 128){
            float u = 0.f, v = 0.f;
            #pragma unroll
            for(int e=0;e<EE;e++){
                float sc = wes[e];
                u = fmaf(sc, Wm [(PP  + e)*MM + p], u);
                v = fmaf(sc, Wc1[(2*PP+ e)*PP + p], v);
            }
            g_U[p] = u;
            g_V[p] = v;
            if(p == 0) g_flag = (bad == 0) ? 1 : 0;
        }
    }
}

// ================================================================ K2: agg + update/gate + NA/CA (512 thr, 2 rows/quarter)
__global__ void __launch_bounds__(512) k_mid(
        const float* __restrict__ Wu, const float* __restrict__ bu,
        const float* __restrict__ Wg, const float* __restrict__ bg,
        const float* __restrict__ Wc1,const float* __restrict__ bm,
        const float* __restrict__ Wm, const float* __restrict__ We,
        const float* __restrict__ be){
    int bx = blockIdx.x;
    int dt = bx & 15, s = bx >> 4, d0 = dt*8;
    int tid = threadIdx.x, p = tid & 127, qf = tid >> 7;   // quarter qf owns rows qf*2, qf*2+1

    __shared__ __align__(16) int   js[8][128];
    __shared__ __align__(16) float ws[8][128];
    __shared__ __align__(16) int   cnts[8];
    __shared__ __align__(16) int   rowFb[8];
    __shared__ __align__(16) float cat[8][PP+MM];
    __shared__ __align__(16) float hs[8][PP];

    if(tid < 8){
        cnts[tid]  = g_cnt[d0 + tid];
        rowFb[tid] = g_flag ? 0 : 1;
    }
    __syncthreads();
    for(int it=tid; it<1024; it+=512){
        int r = it>>7, c = it&127;
        int base = (d0+r)*DN + c;
        js[r][c] = g_nbr[base];
        float w = g_nw[base];
        ws[r][c] = w;
        if(c < cnts[r] && w < 0.f) rowFb[r] = 1;
    }
    for(int it=tid; it<8*PP; it+=512){
        int r = it>>7, c = it&127;
        cat[r][c] = g_enc[(s*DN+d0+r)*PP+c];
    }
    __syncthreads();

    // -------- aggregation: 2 rows per quarter
    float Um = g_U[p], bmm = bm[p];
    #pragma unroll
    for(int rr=0;rr<2;rr++){
        int r = qf*2 + rr;
        int cnt = cnts[r];
        float a = 0.f;
        if(!rowFb[r]){
            for(int k=0;k<cnt;k++){
                int j = js[r][k];
                float b = fmaf(ws[r][k], Um, bmm);
                a = fmaxf(a, g_A[(s*DN + j)*MM + p] + b);
            }
        }else{
            for(int k=0;k<cnt;k++){
                int j = js[r][k];
                float wk = ws[r][k];
                float b = bmm;
                #pragma unroll
                for(int e=0;e<EE;e++){
                    float v = fmaxf(fmaf(wk, We[e], be[e]), 0.f);
                    b = fmaf(v, Wm[(PP+e)*MM + p], b);
                }
                a = fmaxf(a, g_A[(s*DN + j)*MM + p] + b);
            }
        }
        cat[r][PP + p] = a;
    }
    __syncthreads();

    // -------- update + gate (combined, direct LDG weights)
    float u[2], g[2];
    float bup = bu[p], bgp = bg[p];
    #pragma unroll
    for(int r=0;r<2;r++){ u[r]=bup; g[r]=bgp; }
    #pragma unroll 2
    for(int k=0;k<PP+MM;k+=4){
        float u0=Wu[(k)*PP+p], u1=Wu[(k+1)*PP+p], u2=Wu[(k+2)*PP+p], u3=Wu[(k+3)*PP+p];
        float g0=Wg[(k)*PP+p], g1=Wg[(k+1)*PP+p], g2=Wg[(k+2)*PP+p], g3=Wg[(k+3)*PP+p];
        #pragma unroll
        for(int rr=0;rr<2;rr++){
            float4 c = *(const float4*)&cat[qf*2+rr][k];
            u[rr]=fmaf(c.x,u0,u[rr]); u[rr]=fmaf(c.y,u1,u[rr]);
            u[rr]=fmaf(c.z,u2,u[rr]); u[rr]=fmaf(c.w,u3,u[rr]);
            g[rr]=fmaf(c.x,g0,g[rr]); g[rr]=fmaf(c.y,g1,g[rr]);
            g[rr]=fmaf(c.z,g2,g[rr]); g[rr]=fmaf(c.w,g3,g[rr]);
        }
    }
    #pragma unroll
    for(int rr=0;rr<2;rr++){
        int r = qf*2+rr;
        float up = fmaxf(u[rr], 0.f);
        float gg = 1.f / (1.f + __expf(-g[rr]));
        float hv = gg*up + (1.f - gg)*cat[r][p];
        g_hg[(s*DN+d0+r)*PP+p] = hv;
        hs[r][p] = hv;
    }
    __syncthreads();

    // -------- NA / CA projections (combined, direct LDG weights)
    float a1[2], a2[2];
    #pragma unroll
    for(int r=0;r<2;r++){ a1[r]=0.f; a2[r]=0.f; }
    #pragma unroll 2
    for(int k=0;k<PP;k+=4){
        float n0=Wc1[(k)*PP+p], n1=Wc1[(k+1)*PP+p], n2=Wc1[(k+2)*PP+p], n3=Wc1[(k+3)*PP+p];
        float c0=Wc1[(PP+k)*PP+p], c1=Wc1[(PP+k+1)*PP+p], c2=Wc1[(PP+k+2)*PP+p], c3=Wc1[(PP+k+3)*PP+p];
        #pragma unroll
        for(int rr=0;rr<2;rr++){
            float4 h = *(const float4*)&hs[qf*2+rr][k];
            a1[rr]=fmaf(h.x,n0,a1[rr]); a1[rr]=fmaf(h.y,n1,a1[rr]);
            a1[rr]=fmaf(h.z,n2,a1[rr]); a1[rr]=fmaf(h.w,n3,a1[rr]);
            a2[rr]=fmaf(h.x,c0,a2[rr]); a2[rr]=fmaf(h.y,c1,a2[rr]);
            a2[rr]=fmaf(h.z,c2,a2[rr]); a2[rr]=fmaf(h.w,c3,a2[rr]);
        }
    }
    #pragma unroll
    for(int rr=0;rr<2;rr++){
        int r = qf*2+rr;
        g_NA[(s*DN+d0+r)*PP+p] = a1[rr];
        g_CA[(s*DN+d0+r)*PP+p] = a2[rr];
    }
}

// ================================================================ K3: logits (4-t chunks, 512 blocks) + dist (256 blocks)
__global__ void __launch_bounds__(256) k_back(
        const float* __restrict__ Wc1,const float* __restrict__ Wc2,
        const float* __restrict__ bc2,const float* __restrict__ bc1,
        const float* __restrict__ We, const float* __restrict__ be,
        const float* __restrict__ Wd1,const float* __restrict__ bd1,
        const float* __restrict__ Wd2,const float* __restrict__ bd2,
        float* __restrict__ out){
    int bx = blockIdx.x, tid = threadIdx.x;

    if(bx < 512){
        // ---------------- logits: node i, 4 timesteps
        int i = bx & 127, t0 = (bx >> 7) * 4;
        int lane = tid & 31, wp = tid >> 5;
        __shared__ __align__(16) int   js[128];
        __shared__ __align__(16) float ws[128];
        __shared__ __align__(16) int   sFb[4];
        if(tid == 0){ sFb[1] = g_cnt[i]; sFb[0] = g_flag ? 0 : 1; }
        __syncthreads();
        int cnt = sFb[1];
        if(tid < 128){
            js[tid] = g_nbr[i*DN + tid];
            float w = g_nw[i*DN + tid];
            ws[tid] = w;
            if(tid < cnt && w < 0.f) sFb[0] = 1;
        }
        __syncthreads();

        float4 wc  = *(const float4*)&Wc2[lane*4];
        float bc2v = bc2[0];
        float4 V4  = *(const float4*)&g_V[lane*4];
        float4 bC4 = *(const float4*)&bc1[lane*4];
        int fb = sFb[0];
        float4 na[4];
        #pragma unroll
        for(int t=0;t<4;t++) na[t] = *(const float4*)&g_NA[((t0+t+1)*DN + i)*PP + lane*4];

        for(int k=wp; k<cnt; k+=8){
            int j = js[k];
            float wv = ws[k];
            float4 e1;
            if(!fb){
                e1.x = fmaf(wv, V4.x, bC4.x); e1.y = fmaf(wv, V4.y, bC4.y);
                e1.z = fmaf(wv, V4.z, bC4.z); e1.w = fmaf(wv, V4.w, bC4.w);
            }else{
                e1 = bC4;
                #pragma unroll
                for(int e=0;e<EE;e++){
                    float v = fmaxf(fmaf(wv, We[e], be[e]), 0.f);
                    e1.x = fmaf(v, Wc1[(2*PP+e)*PP + lane*4 + 0], e1.x);
                    e1.y = fmaf(v, Wc1[(2*PP+e)*PP + lane*4 + 1], e1.y);
                    e1.z = fmaf(v, Wc1[(2*PP+e)*PP + lane*4 + 2], e1.z);
                    e1.w = fmaf(v, Wc1[(2*PP+e)*PP + lane*4 + 3], e1.w);
                }
            }
            #pragma unroll
            for(int t=0;t<4;t++){
                float4 ca = *(const float4*)&g_CA[((t0+t)*DN + j)*PP + lane*4];
                float s;
                s  = fmaxf(na[t].x + ca.x + e1.x, 0.f) * wc.x;
                s += fmaxf(na[t].y + ca.y + e1.y, 0.f) * wc.y;
                s += fmaxf(na[t].z + ca.z + e1.z, 0.f) * wc.z;
                s += fmaxf(na[t].w + ca.w + e1.w, 0.f) * wc.w;
                #pragma unroll
                for(int off=16; off; off>>=1) s += __shfl_xor_sync(0xffffffffu, s, off);
                if(lane == 0) out[(t0+t)*DN*DN + i*DN + j] = s + bc2v;
            }
        }
        return;
    }
    bx -= 512;

    // ---------------- dist head: 8 nodes, 1 timestep
    {
        int dt = bx & 15, t = bx >> 4, d0 = dt*8;
        int p = tid & 127, hf = tid >> 7;
        __shared__ __align__(16) float df[8][2*PP];
        __shared__ __align__(16) float red[8][PP];
        for(int it=tid; it<8*PP; it+=256){
            int q = it>>3, r = it&7;
            df[r][q]    = g_hg[( t    *DN + d0+r)*PP + q];
            df[r][PP+q] = g_hg[((t+1)*DN + d0+r)*PP + q];
        }
        __syncthreads();
        float acc[4];
        float b = bd1[p];
        #pragma unroll
        for(int r=0;r<4;r++) acc[r] = b;
        #pragma unroll 2
        for(int k=0;k<2*PP;k+=4){
            float w0=Wd1[(k)*PP+p], w1=Wd1[(k+1)*PP+p], w2=Wd1[(k+2)*PP+p], w3=Wd1[(k+3)*PP+p];
            #pragma unroll
            for(int rr=0;rr<4;rr++){
                float4 c = *(const float4*)&df[hf*4+rr][k];
                acc[rr]=fmaf(c.x,w0,acc[rr]); acc[rr]=fmaf(c.y,w1,acc[rr]);
                acc[rr]=fmaf(c.z,w2,acc[rr]); acc[rr]=fmaf(c.w,w3,acc[rr]);
            }
        }
        float wd = Wd2[p];
        #pragma unroll
        for(int rr=0;rr<4;rr++) red[hf*4+rr][p] = fmaxf(acc[rr], 0.f) * wd;
        __syncthreads();
        int r = tid >> 5;
        int lane = tid & 31;
        float sv = red[r][lane] + red[r][lane+32] + red[r][lane+64] + red[r][lane+96];
        #pragma unroll
        for(int off=16; off; off>>=1) sv += __shfl_xor_sync(0xffffffffu, sv, off);
        if(lane == 0) out[TM*DN*DN + t*DN + d0 + r] = sv + bd2[0];
    }
}

// ================================================================ host launcher
extern "C" void kernel_launch(void* const* d_in, const int* in_sizes, int n_in,
                              void* d_out, int out_size){
    struct Exp { int sz; bool opt; };
    static const Exp exp_[23] = {
        {557056,false}, // x
        {16384 ,false}, // edge_w
        {128   ,true }, // batch
        {1     ,true }, // no_graphs
        {2     ,true }, // time_i
        {32768 ,false},{128,false},          // Wn, bn
        {32    ,false},{32 ,false},          // We, be
        {20480 ,false},{128,false},          // Wm, bm
        {32768 ,false},{128,false},          // Wu, bu
        {32768 ,false},{128,false},          // Wg, bg
        {36864 ,false},{128,false},          // Wc1, bc1
        {128   ,false},{1  ,false},          // Wc2, bc2
        {32768 ,false},{128,false},          // Wd1, bd1
        {128   ,false},{1  ,false},          // Wd2, bd2
    };
    const void* ptr[23] = {};
    int pos = 0;
    for(int e=0;e<23;e++){
        if(pos < n_in && in_sizes[pos] == exp_[e].sz){ ptr[e] = d_in[pos]; pos++; }
        else if(exp_[e].opt){ ptr[e] = nullptr; }
        else if(pos < n_in){ ptr[e] = d_in[pos]; pos++; }
    }
    const float* x    = (const float*)ptr[0];
    const float* ew   = (const float*)ptr[1];
    const float* Wn   = (const float*)ptr[5];
    const float* bn   = (const float*)ptr[6];
    const float* We   = (const float*)ptr[7];
    const float* be   = (const float*)ptr[8];
    const float* Wm   = (const float*)ptr[9];
    const float* bm   = (const float*)ptr[10];
    const float* Wu   = (const float*)ptr[11];
    const float* bu   = (const float*)ptr[12];
    const float* Wg   = (const float*)ptr[13];
    const float* bg   = (const float*)ptr[14];
    const float* Wc1  = (const float*)ptr[15];
    const float* bc1  = (const float*)ptr[16];
    const float* Wc2  = (const float*)ptr[17];
    const float* bc2  = (const float*)ptr[18];
    const float* Wd1  = (const float*)ptr[19];
    const float* bd1  = (const float*)ptr[20];
    const float* Wd2  = (const float*)ptr[21];
    const float* bd2  = (const float*)ptr[22];
    float* out = (float*)d_out;

    k_front<<<544 + 128 + 8 + 1, 512>>>(x, Wn, bn, Wm, ew, We, be, Wc1, out);
    k_mid  <<<272, 512>>>(Wu, bu, Wg, bg, Wc1, bm, Wm, We, be);
    k_back <<<512 + 256, 256>>>(Wc1, Wc2, bc2, bc1, We, be, Wd1, bd1, Wd2, bd2, out);
}

// round 16
// speedup vs baseline: 1.3719x; 1.3719x over previous
#include <cuda_runtime.h>

#define TT 17
#define TM 16
#define DN 128
#define HH 256
#define PP 128
#define EE 32
#define MM 128

// scratch (no allocations allowed)
__device__ __align__(16) float g_enc[TT*DN*PP];
__device__ __align__(16) float g_A  [TT*DN*MM];
__device__ __align__(16) float g_hg [TT*DN*PP];
__device__ __align__(16) float g_NA [TT*DN*PP];
__device__ __align__(16) float g_CA [TT*DN*PP];
__device__ __align__(16) float g_U  [MM];
__device__ __align__(16) float g_V  [PP];
__device__ int   g_nbr[DN*DN];
__device__ float g_nw [DN*DN];
__device__ int   g_cnt[DN];
__device__ int   g_flag;   // 1 => be==0, rank-1 edge shortcut valid (modulo per-row w<0 check)

// ---------------- cp.async helpers
__device__ __forceinline__ void cp16(void* dst, const void* src){
    unsigned d = (unsigned)__cvta_generic_to_shared(dst);
    asm volatile("cp.async.ca.shared.global [%0], [%1], 16;\n" :: "r"(d), "l"(src));
}
__device__ __forceinline__ void cpcommit(){ asm volatile("cp.async.commit_group;\n"); }
template<int N> __device__ __forceinline__ void cpwait(){ asm volatile("cp.async.wait_group %0;\n" :: "n"(N)); }
__device__ __forceinline__ void cpwait_rem(int rem){
    if(rem >= 2)      cpwait<2>();
    else if(rem == 1) cpwait<1>();
    else              cpwait<0>();
}

// stage a 16x128-float tile (8 KB) with 512 threads (one float4 per thread)
__device__ __forceinline__ void stageT(float* buf, const float* W, int kt, int tid){
    cp16((float4*)buf + tid, (const float4*)W + kt*512 + tid);
}

// ================================================================ K1: encA + init + nbr + prep
// (4-buffer ring, ONE __syncthreads per k-tile; sync ALWAYS follows cpwait)
__global__ void __launch_bounds__(512) k_front(
        const float* __restrict__ x,  const float* __restrict__ Wn,
        const float* __restrict__ bn, const float* __restrict__ Wm,
        const float* __restrict__ ew, const float* __restrict__ We,
        const float* __restrict__ be, const float* __restrict__ Wc1,
        float* __restrict__ out){
    int bx = blockIdx.x, tid = threadIdx.x;

    if(bx < 272){
        // ---------------- encoder + A projection (8 rows, 1 timestep)
        int dt = bx & 15, s = bx >> 4, d0 = dt*8;
        int p = tid & 127, qf = tid >> 7;              // quarter qf handles rows qf*2, qf*2+1
        __shared__ __align__(16) float xr[8][HH];      // 8 KB
        __shared__ __align__(16) float wb[4][16*128];  // 32 KB ring
        __shared__ __align__(16) float hs[8][PP];      // 4 KB

        // prologue: stage GEMM1 tiles 0..2
        stageT(wb[0], Wn, 0, tid); cpcommit();
        stageT(wb[1], Wn, 1, tid); cpcommit();
        stageT(wb[2], Wn, 2, tid); cpcommit();
        for(int it=tid; it<8*HH; it+=512){
            int h = it>>3, r = it&7;
            xr[r][h] = x[(s*HH+h)*DN + d0 + r];
        }
        float acc[2];
        float b = bn[p];
        acc[0] = b; acc[1] = b;

        // GEMM1: enc = relu(x @ Wn + bn), k=256 in 16 tiles of 16; ONE sync/tile
        for(int kt=0; kt<16; kt++){
            cpwait_rem(15 - kt < 2 ? 15 - kt : 2);
            __syncthreads();   // tile-kt copies visible to all; compute(kt-1) reads done
            if(kt+3 < 16){ stageT(wb[(kt+3)&3], Wn, kt+3, tid); cpcommit(); }
            const float* W = wb[kt&3];
            #pragma unroll
            for(int k=0;k<16;k+=4){
                float w0=W[(k  )*128+p], w1=W[(k+1)*128+p];
                float w2=W[(k+2)*128+p], w3=W[(k+3)*128+p];
                #pragma unroll
                for(int rr=0;rr<2;rr++){
                    float4 xv = *(const float4*)&xr[qf*2+rr][kt*16+k];
                    acc[rr]=fmaf(xv.x,w0,acc[rr]); acc[rr]=fmaf(xv.y,w1,acc[rr]);
                    acc[rr]=fmaf(xv.z,w2,acc[rr]); acc[rr]=fmaf(xv.w,w3,acc[rr]);
                }
            }
        }
        __syncthreads();                                        // all ring reads done
        #pragma unroll
        for(int rr=0;rr<2;rr++){
            float v = fmaxf(acc[rr], 0.f);
            g_enc[(s*DN+d0+qf*2+rr)*PP+p] = v;
            hs[qf*2+rr][p] = v;
        }
        // GEMM2: A = enc @ Wm[:P], k=128 in 8 tiles of 16
        stageT(wb[0], Wm, 0, tid); cpcommit();
        stageT(wb[1], Wm, 1, tid); cpcommit();
        stageT(wb[2], Wm, 2, tid); cpcommit();
        float a2[2];
        a2[0] = 0.f; a2[1] = 0.f;
        for(int kt=0; kt<8; kt++){
            cpwait_rem(7 - kt < 2 ? 7 - kt : 2);
            __syncthreads();   // UNCONDITIONAL: tile-kt copies + hs visible to all
            if(kt+3 < 8){ stageT(wb[(kt+3)&3], Wm, kt+3, tid); cpcommit(); }
            const float* W = wb[kt&3];
            #pragma unroll
            for(int k=0;k<16;k+=4){
                float w0=W[(k  )*128+p], w1=W[(k+1)*128+p];
                float w2=W[(k+2)*128+p], w3=W[(k+3)*128+p];
                #pragma unroll
                for(int rr=0;rr<2;rr++){
                    float4 hv = *(const float4*)&hs[qf*2+rr][kt*16+k];
                    a2[rr]=fmaf(hv.x,w0,a2[rr]); a2[rr]=fmaf(hv.y,w1,a2[rr]);
                    a2[rr]=fmaf(hv.z,w2,a2[rr]); a2[rr]=fmaf(hv.w,w3,a2[rr]);
                }
            }
        }
        #pragma unroll
        for(int rr=0;rr<2;rr++) g_A[(s*DN+d0+qf*2+rr)*MM+p] = a2[rr];
        return;
    }
    bx -= 272;

    if(bx < 128){
        // ---------------- init logits region to -1e9 (128 blk * 512 thr * 16B = 1 MB)
        ((float4*)out)[bx*512 + tid] = make_float4(-1e9f,-1e9f,-1e9f,-1e9f);
        return;
    }
    bx -= 128;

    if(bx < 8){
        // ---------------- neighbor lists: one row per warp (16 warps/block)
        int lane = tid & 31, wpi = tid >> 5;
        int i = bx*16 + wpi;
        int off = 0;
        #pragma unroll
        for(int c=0;c<4;c++){
            int j = c*32 + lane;
            float wv = ew[i*DN + j];
            bool pred = (wv > 0.f) || (j == i);
            unsigned m = __ballot_sync(0xffffffffu, pred);
            if(pred){
                int pos = off + __popc(m & ((1u<<lane)-1u));
                g_nbr[i*DN + pos] = j;
                g_nw [i*DN + pos] = wv;
            }
            off += __popc(m);
        }
        if(lane == 0) g_cnt[i] = off;
        return;
    }

    // ---------------- rank-1 edge precompute + flag (single block)
    {
        int p = tid;
        __shared__ __align__(16) float wes[EE];
        __shared__ int bad;
        if(p == 0) bad = 0;
        __syncthreads();
        if(p < EE){
            wes[p] = fmaxf(We[p], 0.f);
            if(be[p] != 0.f) atomicAdd(&bad, 1);
        }
        __syncthreads();
        if(p < 128){
            float u = 0.f, v = 0.f;
            #pragma unroll
            for(int e=0;e<EE;e++){
                float sc = wes[e];
                u = fmaf(sc, Wm [(PP  + e)*MM + p], u);
                v = fmaf(sc, Wc1[(2*PP+ e)*PP + p], v);
            }
            g_U[p] = u;
            g_V[p] = v;
            if(p == 0) g_flag = (bad == 0) ? 1 : 0;
        }
    }
}

// ================================================================ K2: agg + update/gate + NA/CA (R5/R9 proven version)
__global__ void __launch_bounds__(256) k_mid(
        const float* __restrict__ Wu, const float* __restrict__ bu,
        const float* __restrict__ Wg, const float* __restrict__ bg,
        const float* __restrict__ Wc1,const float* __restrict__ bm,
        const float* __restrict__ Wm, const float* __restrict__ We,
        const float* __restrict__ be){
    int bx = blockIdx.x;
    int dt = bx % 16, s = bx / 16, d0 = dt*8;
    int tid = threadIdx.x, p = tid & 127, hf = tid >> 7;

    __shared__ __align__(16) int   js[8][128];
    __shared__ __align__(16) float ws[8][128];
    __shared__ __align__(16) int   cnts[8];
    __shared__ __align__(16) int   rowFb[8];
    __shared__ __align__(16) float cat[8][PP+MM];
    __shared__ __align__(16) float hs[8][PP];

    if(tid < 8){
        cnts[tid]  = g_cnt[d0 + tid];
        rowFb[tid] = g_flag ? 0 : 1;
    }
    __syncthreads();
    for(int it=tid; it<1024; it+=256){
        int r = it>>7, c = it&127;
        int base = (d0+r)*DN + c;
        js[r][c] = g_nbr[base];
        float w = g_nw[base];
        ws[r][c] = w;
        if(c < cnts[r] && w < 0.f) rowFb[r] = 1;
    }
    for(int it=tid; it<8*PP; it+=256){
        int r = it>>7, c = it&127;
        cat[r][c] = g_enc[(s*DN+d0+r)*PP+c];
    }
    __syncthreads();

    float Um = g_U[p], bmm = bm[p];
    #pragma unroll
    for(int rr=0;rr<4;rr++){
        int r = hf*4 + rr;
        int cnt = cnts[r];
        float a = 0.f;
        if(!rowFb[r]){
            for(int k=0;k<cnt;k++){
                int j = js[r][k];
                float b = fmaf(ws[r][k], Um, bmm);
                a = fmaxf(a, g_A[(s*DN + j)*MM + p] + b);
            }
        }else{
            for(int k=0;k<cnt;k++){
                int j = js[r][k];
                float wk = ws[r][k];
                float b = bmm;
                #pragma unroll
                for(int e=0;e<EE;e++){
                    float v = fmaxf(fmaf(wk, We[e], be[e]), 0.f);
                    b = fmaf(v, Wm[(PP+e)*MM + p], b);
                }
                a = fmaxf(a, g_A[(s*DN + j)*MM + p] + b);
            }
        }
        cat[r][PP + p] = a;
    }
    __syncthreads();

    float u[4], g[4];
    float bup = bu[p], bgp = bg[p];
    #pragma unroll
    for(int r=0;r<4;r++){ u[r]=bup; g[r]=bgp; }
    #pragma unroll 2
    for(int k=0;k<PP+MM;k+=4){
        float u0=Wu[(k)*PP+p], u1=Wu[(k+1)*PP+p], u2=Wu[(k+2)*PP+p], u3=Wu[(k+3)*PP+p];
        float g0=Wg[(k)*PP+p], g1=Wg[(k+1)*PP+p], g2=Wg[(k+2)*PP+p], g3=Wg[(k+3)*PP+p];
        #pragma unroll
        for(int rr=0;rr<4;rr++){
            float4 c = *(const float4*)&cat[hf*4+rr][k];
            u[rr]=fmaf(c.x,u0,u[rr]); u[rr]=fmaf(c.y,u1,u[rr]);
            u[rr]=fmaf(c.z,u2,u[rr]); u[rr]=fmaf(c.w,u3,u[rr]);
            g[rr]=fmaf(c.x,g0,g[rr]); g[rr]=fmaf(c.y,g1,g[rr]);
            g[rr]=fmaf(c.z,g2,g[rr]); g[rr]=fmaf(c.w,g3,g[rr]);
        }
    }
    #pragma unroll
    for(int rr=0;rr<4;rr++){
        int r = hf*4+rr;
        float up = fmaxf(u[rr], 0.f);
        float gg = 1.f / (1.f + __expf(-g[rr]));
        float hv = gg*up + (1.f - gg)*cat[r][p];
        g_hg[(s*DN+d0+r)*PP+p] = hv;
        hs[r][p] = hv;
    }
    __syncthreads();

    float a1[4], a2[4];
    #pragma unroll
    for(int r=0;r<4;r++){ a1[r]=0.f; a2[r]=0.f; }
    #pragma unroll 2
    for(int k=0;k<PP;k+=4){
        float n0=Wc1[(k)*PP+p], n1=Wc1[(k+1)*PP+p], n2=Wc1[(k+2)*PP+p], n3=Wc1[(k+3)*PP+p];
        float c0=Wc1[(PP+k)*PP+p], c1=Wc1[(PP+k+1)*PP+p], c2=Wc1[(PP+k+2)*PP+p], c3=Wc1[(PP+k+3)*PP+p];
        #pragma unroll
        for(int rr=0;rr<4;rr++){
            float4 h = *(const float4*)&hs[hf*4+rr][k];
            a1[rr]=fmaf(h.x,n0,a1[rr]); a1[rr]=fmaf(h.y,n1,a1[rr]);
            a1[rr]=fmaf(h.z,n2,a1[rr]); a1[rr]=fmaf(h.w,n3,a1[rr]);
            a2[rr]=fmaf(h.x,c0,a2[rr]); a2[rr]=fmaf(h.y,c1,a2[rr]);
            a2[rr]=fmaf(h.z,c2,a2[rr]); a2[rr]=fmaf(h.w,c3,a2[rr]);
        }
    }
    #pragma unroll
    for(int rr=0;rr<4;rr++){
        int r = hf*4+rr;
        g_NA[(s*DN+d0+r)*PP+p] = a1[rr];
        g_CA[(s*DN+d0+r)*PP+p] = a2[rr];
    }
}

// ================================================================ K3: logits + dist (R5/R9 proven version)
__global__ void __launch_bounds__(256) k_back(
        const float* __restrict__ Wc1,const float* __restrict__ Wc2,
        const float* __restrict__ bc2,const float* __restrict__ bc1,
        const float* __restrict__ We, const float* __restrict__ be,
        const float* __restrict__ Wd1,const float* __restrict__ bd1,
        const float* __restrict__ Wd2,const float* __restrict__ bd2,
        float* __restrict__ out){
    int bx = blockIdx.x, tid = threadIdx.x;

    if(bx < 256){
        int i = bx & 127, t0 = (bx >> 7) * 8;
        int lane = tid & 31, wp = tid >> 5;
        __shared__ __align__(16) int   js[128];
        __shared__ __align__(16) float ws[128];
        __shared__ __align__(16) int   sFb[4];
        if(tid == 0){ sFb[1] = g_cnt[i]; sFb[0] = g_flag ? 0 : 1; }
        __syncthreads();
        int cnt = sFb[1];
        if(tid < 128){
            js[tid] = g_nbr[i*DN + tid];
            float w = g_nw[i*DN + tid];
            ws[tid] = w;
            if(tid < cnt && w < 0.f) sFb[0] = 1;
        }
        __syncthreads();

        float4 wc  = *(const float4*)&Wc2[lane*4];
        float bc2v = bc2[0];
        float4 V4  = *(const float4*)&g_V[lane*4];
        float4 bC4 = *(const float4*)&bc1[lane*4];
        int fb = sFb[0];
        float4 na[8];
        #pragma unroll
        for(int t=0;t<8;t++) na[t] = *(const float4*)&g_NA[((t0+t+1)*DN + i)*PP + lane*4];

        for(int k=wp; k<cnt; k+=8){
            int j = js[k];
            float wv = ws[k];
            float4 e1;
            if(!fb){
                e1.x = fmaf(wv, V4.x, bC4.x); e1.y = fmaf(wv, V4.y, bC4.y);
                e1.z = fmaf(wv, V4.z, bC4.z); e1.w = fmaf(wv, V4.w, bC4.w);
            }else{
                e1 = bC4;
                #pragma unroll
                for(int e=0;e<EE;e++){
                    float v = fmaxf(fmaf(wv, We[e], be[e]), 0.f);
                    e1.x = fmaf(v, Wc1[(2*PP+e)*PP + lane*4 + 0], e1.x);
                    e1.y = fmaf(v, Wc1[(2*PP+e)*PP + lane*4 + 1], e1.y);
                    e1.z = fmaf(v, Wc1[(2*PP+e)*PP + lane*4 + 2], e1.z);
                    e1.w = fmaf(v, Wc1[(2*PP+e)*PP + lane*4 + 3], e1.w);
                }
            }
            #pragma unroll
            for(int t=0;t<8;t++){
                float4 ca = *(const float4*)&g_CA[((t0+t)*DN + j)*PP + lane*4];
                float s;
                s  = fmaxf(na[t].x + ca.x + e1.x, 0.f) * wc.x;
                s += fmaxf(na[t].y + ca.y + e1.y, 0.f) * wc.y;
                s += fmaxf(na[t].z + ca.z + e1.z, 0.f) * wc.z;
                s += fmaxf(na[t].w + ca.w + e1.w, 0.f) * wc.w;
                #pragma unroll
                for(int off=16; off; off>>=1) s += __shfl_xor_sync(0xffffffffu, s, off);
                if(lane == 0) out[(t0+t)*DN*DN + i*DN + j] = s + bc2v;
            }
        }
        return;
    }
    bx -= 256;

    {
        int dt = bx % 16, t = bx / 16, d0 = dt*8;
        int p = tid & 127, hf = tid >> 7;
        __shared__ __align__(16) float df[8][2*PP];
        __shared__ __align__(16) float red[8][PP];
        for(int it=tid; it<8*PP; it+=256){
            int q = it>>3, r = it&7;
            df[r][q]    = g_hg[( t    *DN + d0+r)*PP + q];
            df[r][PP+q] = g_hg[((t+1)*DN + d0+r)*PP + q];
        }
        __syncthreads();
        float acc[4];
        float b = bd1[p];
        #pragma unroll
        for(int r=0;r<4;r++) acc[r] = b;
        #pragma unroll 2
        for(int k=0;k<2*PP;k+=4){
            float w0=Wd1[(k)*PP+p], w1=Wd1[(k+1)*PP+p], w2=Wd1[(k+2)*PP+p], w3=Wd1[(k+3)*PP+p];
            #pragma unroll
            for(int rr=0;rr<4;rr++){
                float4 c = *(const float4*)&df[hf*4+rr][k];
                acc[rr]=fmaf(c.x,w0,acc[rr]); acc[rr]=fmaf(c.y,w1,acc[rr]);
                acc[rr]=fmaf(c.z,w2,acc[rr]); acc[rr]=fmaf(c.w,w3,acc[rr]);
            }
        }
        float wd = Wd2[p];
        #pragma unroll
        for(int rr=0;rr<4;rr++) red[hf*4+rr][p] = fmaxf(acc[rr], 0.f) * wd;
        __syncthreads();
        int r = tid >> 5;
        int lane = tid & 31;
        float sv = red[r][lane] + red[r][lane+32] + red[r][lane+64] + red[r][lane+96];
        #pragma unroll
        for(int off=16; off; off>>=1) sv += __shfl_xor_sync(0xffffffffu, sv, off);
        if(lane == 0) out[TM*DN*DN + t*DN + d0 + r] = sv + bd2[0];
    }
}

// ================================================================ host launcher
extern "C" void kernel_launch(void* const* d_in, const int* in_sizes, int n_in,
                              void* d_out, int out_size){
    struct Exp { int sz; bool opt; };
    static const Exp exp_[23] = {
        {557056,false}, // x
        {16384 ,false}, // edge_w
        {128   ,true }, // batch
        {1     ,true }, // no_graphs
        {2     ,true }, // time_i
        {32768 ,false},{128,false},          // Wn, bn
        {32    ,false},{32 ,false},          // We, be
        {20480 ,false},{128,false},          // Wm, bm
        {32768 ,false},{128,false},          // Wu, bu
        {32768 ,false},{128,false},          // Wg, bg
        {36864 ,false},{128,false},          // Wc1, bc1
        {128   ,false},{1  ,false},          // Wc2, bc2
        {32768 ,false},{128,false},          // Wd1, bd1
        {128   ,false},{1  ,false},          // Wd2, bd2
    };
    const void* ptr[23] = {};
    int pos = 0;
    for(int e=0;e<23;e++){
        if(pos < n_in && in_sizes[pos] == exp_[e].sz){ ptr[e] = d_in[pos]; pos++; }
        else if(exp_[e].opt){ ptr[e] = nullptr; }
        else if(pos < n_in){ ptr[e] = d_in[pos]; pos++; }
    }
    const float* x    = (const float*)ptr[0];
    const float* ew   = (const float*)ptr[1];
    const float* Wn   = (const float*)ptr[5];
    const float* bn   = (const float*)ptr[6];
    const float* We   = (const float*)ptr[7];
    const float* be   = (const float*)ptr[8];
    const float* Wm   = (const float*)ptr[9];
    const float* bm   = (const float*)ptr[10];
    const float* Wu   = (const float*)ptr[11];
    const float* bu   = (const float*)ptr[12];
    const float* Wg   = (const float*)ptr[13];
    const float* bg   = (const float*)ptr[14];
    const float* Wc1  = (const float*)ptr[15];
    const float* bc1  = (const float*)ptr[16];
    const float* Wc2  = (const float*)ptr[17];
    const float* bc2  = (const float*)ptr[18];
    const float* Wd1  = (const float*)ptr[19];
    const float* bd1  = (const float*)ptr[20];
    const float* Wd2  = (const float*)ptr[21];
    const float* bd2  = (const float*)ptr[22];
    float* out = (float*)d_out;

    k_front<<<272 + 128 + 8 + 1, 512>>>(x, Wn, bn, Wm, ew, We, be, Wc1, out);
    k_mid  <<<272, 256>>>(Wu, bu, Wg, bg, Wc1, bm, Wm, We, be);
    k_back <<<512, 256>>>(Wc1, Wc2, bc2, bc1, We, be, Wd1, bd1, Wd2, bd2, out);
}